// round 5
// baseline (speedup 1.0000x reference)
#include <cuda_runtime.h>
#include <cstdint>

// ---------------- Problem constants ----------------
#define E_TOTAL   500000
#define TILE_M    128
#define NTILES    ((E_TOTAL + TILE_M - 1) / TILE_M)   // 3907
#define NTHREADS  256

// ---------------- SMEM layout (bytes) ----------------
// W: 5 chunks, each [64 n-rows x 64 k-cols] tf32 = 16KB  -> 80KB
// A: ring of 4 bufs, each [128 rows x 64 k-cols] tf32 = 32KB -> 128KB
// mbarriers: full0..full3, empty0
#define SM_W       0
#define SM_A       (5 * 16384)             // 81920
#define SM_MBAR    (SM_A + 4 * 32768)      // 212992
#define SMEM_TOTAL (SM_MBAR + 64)          // 213056  (< 227KB limit)

// ---------------- helpers ----------------
__device__ __forceinline__ uint32_t smem_u32(const void* p) {
    uint32_t a;
    asm("{ .reg .u64 t; cvta.to.shared.u64 t, %1; cvt.u32.u64 %0, t; }"
        : "=r"(a) : "l"(p));
    return a;
}

__device__ __forceinline__ uint32_t f2tf32(float f) {
    uint32_t r;
    asm("cvt.rna.tf32.f32 %0, %1;" : "=r"(r) : "f"(f));
    return r;
}

// Tile addressing: tiles are [rows x 64 cols] fp32(tf32), row stride 256B.
// Within a row, cols are stored k-permuted per 16-col group:
//   position p = (col%4)*4 + ((col>>2)&3), so a 16B quad at offset tig*16
//   holds cols {16*grp + tig, +4, +8, +12}  -> two mma k-steps per LDS.128.
// Bank swizzle: XOR 16B-position bits[6:4] with row bits[10:8] (row & 7).
__device__ __forceinline__ uint32_t tileoff(int row, int grp, int tig) {
    uint32_t o = (uint32_t)(row * 256 + grp * 64 + tig * 16);
    return o ^ ((o >> 4) & 0x70);
}

__device__ __forceinline__ void sts128(uint32_t addr, uint32_t a, uint32_t b,
                                       uint32_t c, uint32_t d) {
    asm volatile("st.shared.v4.b32 [%0], {%1,%2,%3,%4};"
                 :: "r"(addr), "r"(a), "r"(b), "r"(c), "r"(d) : "memory");
}

__device__ __forceinline__ void lds128(uint32_t addr, uint32_t* r) {
    asm volatile("ld.shared.v4.b32 {%0,%1,%2,%3}, [%4];"
                 : "=r"(r[0]), "=r"(r[1]), "=r"(r[2]), "=r"(r[3])
                 : "r"(addr));
}

// m16n8k8 TF32 mma (row.col): D = A*B + D
__device__ __forceinline__ void mma_tf32(float* c, uint32_t a0, uint32_t a1,
                                         uint32_t a2, uint32_t a3,
                                         uint32_t b0, uint32_t b1) {
    asm volatile(
        "mma.sync.aligned.m16n8k8.row.col.f32.tf32.tf32.f32 "
        "{%0,%1,%2,%3},{%4,%5,%6,%7},{%8,%9},{%0,%1,%2,%3};"
        : "+f"(c[0]), "+f"(c[1]), "+f"(c[2]), "+f"(c[3])
        : "r"(a0), "r"(a1), "r"(a2), "r"(a3), "r"(b0), "r"(b1));
}

#define MBARRIER_INIT(mbar, cnt) \
    asm volatile("mbarrier.init.shared.b64 [%0], %1;" \
                 :: "r"((uint32_t)(mbar)), "r"((uint32_t)(cnt)) : "memory")

#define MBARRIER_ARRIVE(mbar) \
    asm volatile("mbarrier.arrive.shared.b64 _, [%0];" \
                 :: "r"((uint32_t)(mbar)) : "memory")

#define MBARRIER_WAIT_PARITY(mbar, parity) do {                                    \
    uint32_t _m = (uint32_t)(mbar);                                                \
    uint32_t _p = (uint32_t)(parity);                                              \
    asm volatile(                                                                  \
        "{\n\t.reg .pred P1;\n\t"                                                  \
        "WAIT_LOOP_%=:\n\t"                                                        \
        "mbarrier.try_wait.parity.acquire.cta.shared::cta.b64 P1, [%0], %1, 0x989680;\n\t" \
        "@P1 bra.uni WAIT_DONE_%=;\n\t"                                            \
        "bra.uni WAIT_LOOP_%=;\n\t"                                                \
        "WAIT_DONE_%=:\n\t}"                                                       \
        :: "r"(_m), "r"(_p) : "memory");                                           \
} while (0)

// Store one 16-col group (4 float4s = cols 16*grp .. +15) of one row,
// converting to tf32 and repacking into the k-permuted layout with STS.128.
// Quad tau holds components .{x,y,z,w}[tau] of v[0..3] = cols {tau, tau+4, tau+8, tau+12}.
__device__ __forceinline__ void sts_group(uint32_t base, int row, int grp,
                                          const float4* v) {
    const float* f = (const float*)v;   // f[i*4 + j] = v[i] component j
#pragma unroll
    for (int t = 0; t < 4; t++) {
        sts128(base + tileoff(row, grp, t),
               f2tf32(f[0 * 4 + t]), f2tf32(f[1 * 4 + t]),
               f2tf32(f[2 * 4 + t]), f2tf32(f[3 * 4 + t]));
    }
}

// ---------------- producer builds ----------------
__device__ __forceinline__ void build_x(uint32_t base, int r, const float4* xr) {
#pragma unroll
    for (int gp = 0; gp < 4; gp++) {
        float4 v[4];
#pragma unroll
        for (int i = 0; i < 4; i++) v[i] = xr[gp * 4 + i];
        sts_group(base, r, gp, v);
    }
}

__device__ __forceinline__ void build_pair(uint32_t bmin, uint32_t bmax, int r,
                                           const float* __restrict__ x,
                                           const int* __restrict__ nbr,
                                           int e, int p) {
    int2 nn = *(const int2*)(nbr + (size_t)e * 4 + p * 2);
    const bool aok = nn.x >= 0;
    const bool bok = nn.y >= 0;
    const float4* xa = (const float4*)x + (size_t)(aok ? nn.x : 0) * 16;
    const float4* xb = (const float4*)x + (size_t)(bok ? nn.y : 0) * 16;
#pragma unroll
    for (int gp = 0; gp < 4; gp++) {
        float4 a[4], b[4], mn[4], mx[4];
#pragma unroll
        for (int i = 0; i < 4; i++) {
            a[i] = aok ? xa[gp * 4 + i] : make_float4(0.f, 0.f, 0.f, 0.f);
            b[i] = bok ? xb[gp * 4 + i] : make_float4(0.f, 0.f, 0.f, 0.f);
            mn[i] = make_float4(fminf(a[i].x, b[i].x), fminf(a[i].y, b[i].y),
                                fminf(a[i].z, b[i].z), fminf(a[i].w, b[i].w));
            mx[i] = make_float4(fmaxf(a[i].x, b[i].x), fmaxf(a[i].y, b[i].y),
                                fmaxf(a[i].z, b[i].z), fmaxf(a[i].w, b[i].w));
        }
        sts_group(bmin, r, gp, mn);
        sts_group(bmax, r, gp, mx);
    }
}

// ---------------- kernel ----------------
// Combined-column layout (K=320, chunked by 64):
//   chunk 0: x[0:64]   chunk 1: min01   chunk 2: max01   chunk 3: min23   chunk 4: max23
// A ring buffers: c0->buf0, c1->buf1, c2->buf2, c3->buf3, c4->buf0 (after empty0).
__global__ void __launch_bounds__(NTHREADS, 1)
meshconv_kernel(const float* __restrict__ x, const int* __restrict__ nbr,
                const float* __restrict__ W, const float* __restrict__ bias,
                float* __restrict__ out) {
    extern __shared__ char smem[];
    const uint32_t sb = smem_u32(smem);
    const int tid  = threadIdx.x;
    const int tile = blockIdx.x;

    if (tid == 0) {
#pragma unroll
        for (int i = 0; i < 4; i++) MBARRIER_INIT(sb + SM_MBAR + i * 8, 128); // full
        MBARRIER_INIT(sb + SM_MBAR + 32, 128);                               // empty0
    }

    // ---- stage W (all 256 threads): 5 chunks x [64 n-rows x 64 k-cols] ----
    // 1280 group-tasks (n, chunk, grp); each = 4 LDG.128 + 4 STS.128.
#pragma unroll
    for (int it = 0; it < 5; it++) {
        int t = tid + it * NTHREADS;        // 0..1279
        int n = t / 20;
        int rem = t % 20;
        int c = rem >> 2;
        int g = rem & 3;
        float4 v[4];
#pragma unroll
        for (int i = 0; i < 4; i++)
            v[i] = ((const float4*)W)[(size_t)n * 80 + c * 16 + g * 4 + i];
        sts_group(sb + SM_W + (uint32_t)c * 16384u, n, g, v);
    }
    __syncthreads();

    if (tid < 128) {
        // ================= CONSUMER: 4 warps, each m64 x n32 =================
        const int wid = tid >> 5, lid = tid & 31;
        const int wm = wid & 1, wn = wid >> 1;
        const int g = lid >> 2, tig = lid & 3;

        float acc[4][4][4];
#pragma unroll
        for (int a = 0; a < 4; a++)
#pragma unroll
            for (int b = 0; b < 4; b++)
#pragma unroll
                for (int k = 0; k < 4; k++) acc[a][b][k] = 0.f;

        float bv0[4], bv1[4];
#pragma unroll
        for (int nf = 0; nf < 4; nf++) {
            int bc = wn * 32 + nf * 8 + tig * 2;
            bv0[nf] = __ldg(bias + bc);
            bv1[nf] = __ldg(bias + bc + 1);
        }

        for (int c = 0; c < 5; c++) {
            const int buf = (c == 4) ? 0 : c;
            const int par = (c == 4) ? 1 : 0;
            MBARRIER_WAIT_PARITY(sb + SM_MBAR + buf * 8, par);
            const uint32_t aB = sb + SM_A + (uint32_t)buf * 32768u;
            const uint32_t wB = sb + SM_W + (uint32_t)c * 16384u;
#pragma unroll
            for (int t = 0; t < 4; t++) {
                uint32_t Bf[4][4];
#pragma unroll
                for (int nf = 0; nf < 4; nf++)
                    lds128(wB + tileoff(wn * 32 + nf * 8 + g, t, tig), Bf[nf]);
#pragma unroll
                for (int fh = 0; fh < 2; fh++) {
                    uint32_t Af[2][2][4];
#pragma unroll
                    for (int ms = 0; ms < 2; ms++)
#pragma unroll
                        for (int rh = 0; rh < 2; rh++)
                            lds128(aB + tileoff(wm * 64 + (fh * 2 + ms) * 16 + rh * 8 + g,
                                                t, tig),
                                   Af[ms][rh]);
#pragma unroll
                    for (int ms = 0; ms < 2; ms++)
#pragma unroll
                        for (int nf = 0; nf < 4; nf++)
#pragma unroll
                            for (int s = 0; s < 2; s++)
                                mma_tf32(acc[fh * 2 + ms][nf],
                                         Af[ms][0][2 * s], Af[ms][1][2 * s],
                                         Af[ms][0][2 * s + 1], Af[ms][1][2 * s + 1],
                                         Bf[nf][2 * s], Bf[nf][2 * s + 1]);
                }
            }
            if (c == 0) MBARRIER_ARRIVE(sb + SM_MBAR + 32);   // empty0
        }

        // ---- epilogue: bias add + store ----
#pragma unroll
        for (int mf = 0; mf < 4; mf++) {
#pragma unroll
            for (int nf = 0; nf < 4; nf++) {
                const int row0 = wm * 64 + mf * 16 + g;
                const int col  = wn * 32 + nf * 8 + tig * 2;
                const int e0 = tile * TILE_M + row0;
                const int e1 = e0 + 8;
                if (e0 < E_TOTAL) {
                    float2 o;
                    o.x = acc[mf][nf][0] + bv0[nf];
                    o.y = acc[mf][nf][1] + bv1[nf];
                    *(float2*)(out + (size_t)e0 * 64 + col) = o;
                }
                if (e1 < E_TOTAL) {
                    float2 o;
                    o.x = acc[mf][nf][2] + bv0[nf];
                    o.y = acc[mf][nf][3] + bv1[nf];
                    *(float2*)(out + (size_t)e1 * 64 + col) = o;
                }
            }
        }
    } else {
        // ================= PRODUCER: 4 warps, one row per thread =============
        const int r = tid - 128;
        int e = tile * TILE_M + r;
        if (e >= E_TOTAL) e = E_TOTAL - 1;   // clamp; garbage rows discarded in epilogue

        const uint32_t buf0 = sb + SM_A;
        const uint32_t buf1 = buf0 + 32768u;
        const uint32_t buf2 = buf0 + 65536u;
        const uint32_t buf3 = buf0 + 98304u;

        // chunk 0: x
        build_x(buf0, r, (const float4*)x + (size_t)e * 16);
        MBARRIER_ARRIVE(sb + SM_MBAR + 0);

        // chunks 1,2: min/max of neighbor pair 0
        build_pair(buf1, buf2, r, x, nbr, e, 0);
        MBARRIER_ARRIVE(sb + SM_MBAR + 8);
        MBARRIER_ARRIVE(sb + SM_MBAR + 16);

        // chunks 3,4: min/max of neighbor pair 1 (buf0 reuse gated by empty0)
        MBARRIER_WAIT_PARITY(sb + SM_MBAR + 32, 0);
        build_pair(buf3, buf0, r, x, nbr, e, 1);
        MBARRIER_ARRIVE(sb + SM_MBAR + 24);
        MBARRIER_ARRIVE(sb + SM_MBAR + 0);
    }
}

// ---------------- launch ----------------
extern "C" void kernel_launch(void* const* d_in, const int* in_sizes, int n_in,
                              void* d_out, int out_size) {
    const float* x   = (const float*)d_in[0];
    const int*   nbr = (const int*)d_in[1];
    const float* W   = (const float*)d_in[2];
    const float* b   = (const float*)d_in[3];
    float* out = (float*)d_out;

    cudaFuncSetAttribute(meshconv_kernel,
                         cudaFuncAttributeMaxDynamicSharedMemorySize, SMEM_TOTAL);
    meshconv_kernel<<<NTILES, NTHREADS, SMEM_TOTAL>>>(x, nbr, W, b, out);
}

// round 6
// speedup vs baseline: 1.2473x; 1.2473x over previous
#include <cuda_runtime.h>
#include <cstdint>

// ---------------- Problem constants ----------------
#define E_TOTAL   500000
#define TILE_M    128
#define NTILES    ((E_TOTAL + TILE_M - 1) / TILE_M)   // 3907
#define NTHREADS  512

// ---------------- SMEM layout (bytes) ----------------
// W: 5 chunks, each [64 n-rows x 64 k-cols] tf32 = 16KB -> 80KB  (loaded once)
// A: ring of 4 slots, each [128 rows x 64 k-cols] tf32 = 32KB -> 128KB
#define SM_W       0
#define SM_A       (5 * 16384)             // 81920
#define SM_MBAR    (SM_A + 4 * 32768)      // 212992: full[0..3], empty[0..3]
#define SMEM_TOTAL (SM_MBAR + 64)          // 213056  (< 227KB limit)

// ---------------- helpers ----------------
__device__ __forceinline__ uint32_t smem_u32(const void* p) {
    uint32_t a;
    asm("{ .reg .u64 t; cvta.to.shared.u64 t, %1; cvt.u32.u64 %0, t; }"
        : "=r"(a) : "l"(p));
    return a;
}

__device__ __forceinline__ uint32_t f2tf32(float f) {
    uint32_t r;
    asm("cvt.rna.tf32.f32 %0, %1;" : "=r"(r) : "f"(f));
    return r;
}

// Tile layout: [rows x 64 cols] tf32, 256B per row. Cols k-permuted per
// 16-col group: the 16B quad at (grp, tig) holds cols {16*grp + tig, +4, +8, +12}
// -> one LDS.128 feeds two mma k-steps.
// Swizzle (verified conflict-free for all 3 access patterns):
//   XOR 16B-group bits[6:4] with ((row&1)<<2) | (row&2) | ((grp>>1)&1).
//   - consumer loads (rows {a,a+1} x tig 0..3, grp fixed): row&1 flips bit2 -> 8 distinct
//   - producer stores (rows a..a+3 x grp-bit1 {0,1}, tig fixed): rows give
//     {0,2,4,6}, grp>>1 gives bit0 -> 8 distinct
__device__ __forceinline__ uint32_t tileoff(int row, int grp, int tig) {
    uint32_t o  = (uint32_t)(row * 256 + grp * 64 + tig * 16);
    uint32_t sw = (((uint32_t)row & 1u) << 2) | ((uint32_t)row & 2u) |
                  (((uint32_t)grp >> 1) & 1u);
    return o ^ (sw << 4);
}

__device__ __forceinline__ void sts128(uint32_t addr, uint32_t a, uint32_t b,
                                       uint32_t c, uint32_t d) {
    asm volatile("st.shared.v4.b32 [%0], {%1,%2,%3,%4};"
                 :: "r"(addr), "r"(a), "r"(b), "r"(c), "r"(d) : "memory");
}

__device__ __forceinline__ void lds128(uint32_t addr, uint32_t* r) {
    asm volatile("ld.shared.v4.b32 {%0,%1,%2,%3}, [%4];"
                 : "=r"(r[0]), "=r"(r[1]), "=r"(r[2]), "=r"(r[3])
                 : "r"(addr));
}

// m16n8k8 TF32 mma (row.col): D = A*B + D
__device__ __forceinline__ void mma_tf32(float* c, uint32_t a0, uint32_t a1,
                                         uint32_t a2, uint32_t a3,
                                         uint32_t b0, uint32_t b1) {
    asm volatile(
        "mma.sync.aligned.m16n8k8.row.col.f32.tf32.tf32.f32 "
        "{%0,%1,%2,%3},{%4,%5,%6,%7},{%8,%9},{%0,%1,%2,%3};"
        : "+f"(c[0]), "+f"(c[1]), "+f"(c[2]), "+f"(c[3])
        : "r"(a0), "r"(a1), "r"(a2), "r"(a3), "r"(b0), "r"(b1));
}

#define MBARRIER_INIT(mbar, cnt) \
    asm volatile("mbarrier.init.shared.b64 [%0], %1;" \
                 :: "r"((uint32_t)(mbar)), "r"((uint32_t)(cnt)) : "memory")

#define MBARRIER_ARRIVE(mbar) \
    asm volatile("mbarrier.arrive.release.cta.shared::cta.b64 _, [%0];" \
                 :: "r"((uint32_t)(mbar)) : "memory")

#define MBARRIER_WAIT_PARITY(mbar, parity) do {                                    \
    uint32_t _m = (uint32_t)(mbar);                                                \
    uint32_t _p = (uint32_t)(parity);                                              \
    asm volatile(                                                                  \
        "{\n\t.reg .pred P1;\n\t"                                                  \
        "WAIT_LOOP_%=:\n\t"                                                        \
        "mbarrier.try_wait.parity.acquire.cta.shared::cta.b64 P1, [%0], %1, 0x989680;\n\t" \
        "@P1 bra.uni WAIT_DONE_%=;\n\t"                                            \
        "bra.uni WAIT_LOOP_%=;\n\t"                                                \
        "WAIT_DONE_%=:\n\t}"                                                       \
        :: "r"(_m), "r"(_p) : "memory");                                           \
} while (0)

#define FULL_BAR(sb, s)  ((sb) + SM_MBAR + (uint32_t)(s) * 8u)
#define EMPTY_BAR(sb, s) ((sb) + SM_MBAR + 32u + (uint32_t)(s) * 8u)

// Store one 16-col group of one row (4 float4s -> cols 16*grp..+15),
// converting to tf32 and repacking into the k-permuted layout.
__device__ __forceinline__ void sts_group(uint32_t base, int row, int grp,
                                          const float4* v) {
    const float* f = (const float*)v;   // f[i*4 + j] = v[i] component j
#pragma unroll
    for (int t = 0; t < 4; t++) {
        sts128(base + tileoff(row, grp, t),
               f2tf32(f[0 * 4 + t]), f2tf32(f[1 * 4 + t]),
               f2tf32(f[2 * 4 + t]), f2tf32(f[3 * 4 + t]));
    }
}

// ---------------- kernel ----------------
// Combined layout (K=320, chunks of 64):
//   c0: x   c1: min01   c2: max01   c3: min23   c4: max23
// Persistent: each CTA strides over tiles; producers (threads 256..511) fill a
// 4-slot ring continuously; consumers (threads 0..255) drain it.
__global__ void __launch_bounds__(NTHREADS, 1)
meshconv_kernel(const float* __restrict__ x, const int* __restrict__ nbr,
                const float* __restrict__ W, const float* __restrict__ bias,
                float* __restrict__ out) {
    extern __shared__ char smem[];
    const uint32_t sb = smem_u32(smem);
    const int tid = threadIdx.x;

    if (tid == 0) {
#pragma unroll
        for (int s = 0; s < 4; s++) {
            MBARRIER_INIT(FULL_BAR(sb, s), 256);
            MBARRIER_INIT(EMPTY_BAR(sb, s), 256);
        }
    }

    // ---- stage W once: 5 chunks x [64 n x 64 k]; 1280 group-tasks ----
#pragma unroll
    for (int it = 0; it < 3; it++) {
        int t = tid + it * NTHREADS;
        if (t < 1280) {
            int n = t / 20;
            int rem = t % 20;
            int c = rem >> 2;
            int g = rem & 3;
            float4 v[4];
#pragma unroll
            for (int i = 0; i < 4; i++)
                v[i] = ((const float4*)W)[(size_t)n * 80 + c * 16 + g * 4 + i];
            sts_group(sb + SM_W + (uint32_t)c * 16384u, n, g, v);
        }
    }
    __syncthreads();

    if (tid < 256) {
        // ================= CONSUMERS: 8 warps, each m32 x n32 =================
        const int wid = tid >> 5, lid = tid & 31;
        const int wm = wid & 3, wn = wid >> 2;
        const int g = lid >> 2, tig = lid & 3;

        float bv0[4], bv1[4];
#pragma unroll
        for (int nf = 0; nf < 4; nf++) {
            int bc = wn * 32 + nf * 8 + tig * 2;
            bv0[nf] = __ldg(bias + bc);
            bv1[nf] = __ldg(bias + bc + 1);
        }

        int slot = 0, phase = 0;
        for (int tile = blockIdx.x; tile < NTILES; tile += gridDim.x) {
            float acc[2][4][4];
#pragma unroll
            for (int a = 0; a < 2; a++)
#pragma unroll
                for (int b = 0; b < 4; b++)
#pragma unroll
                    for (int k = 0; k < 4; k++) acc[a][b][k] = 0.f;

#pragma unroll
            for (int c = 0; c < 5; c++) {
                MBARRIER_WAIT_PARITY(FULL_BAR(sb, slot), phase);
                const uint32_t wB = sb + SM_W + (uint32_t)c * 16384u;
                const uint32_t aB = sb + SM_A + (uint32_t)slot * 32768u;
#pragma unroll
                for (int t = 0; t < 4; t++) {
                    uint32_t Bf[4][4];
#pragma unroll
                    for (int nf = 0; nf < 4; nf++)
                        lds128(wB + tileoff(wn * 32 + nf * 8 + g, t, tig), Bf[nf]);
                    uint32_t Af[2][2][4];
#pragma unroll
                    for (int ms = 0; ms < 2; ms++)
#pragma unroll
                        for (int rh = 0; rh < 2; rh++)
                            lds128(aB + tileoff(wm * 32 + ms * 16 + rh * 8 + g, t, tig),
                                   Af[ms][rh]);
#pragma unroll
                    for (int ms = 0; ms < 2; ms++)
#pragma unroll
                        for (int nf = 0; nf < 4; nf++)
#pragma unroll
                            for (int s = 0; s < 2; s++)
                                mma_tf32(acc[ms][nf],
                                         Af[ms][0][2 * s], Af[ms][1][2 * s],
                                         Af[ms][0][2 * s + 1], Af[ms][1][2 * s + 1],
                                         Bf[nf][2 * s], Bf[nf][2 * s + 1]);
                }
                MBARRIER_ARRIVE(EMPTY_BAR(sb, slot));
                if (++slot == 4) { slot = 0; phase ^= 1; }
            }

            // ---- epilogue: bias add + store ----
#pragma unroll
            for (int ms = 0; ms < 2; ms++) {
#pragma unroll
                for (int nf = 0; nf < 4; nf++) {
                    const int e0  = tile * TILE_M + wm * 32 + ms * 16 + g;
                    const int e1  = e0 + 8;
                    const int col = wn * 32 + nf * 8 + tig * 2;
                    if (e0 < E_TOTAL) {
                        float2 o;
                        o.x = acc[ms][nf][0] + bv0[nf];
                        o.y = acc[ms][nf][1] + bv1[nf];
                        *(float2*)(out + (size_t)e0 * 64 + col) = o;
                    }
                    if (e1 < E_TOTAL) {
                        float2 o;
                        o.x = acc[ms][nf][2] + bv0[nf];
                        o.y = acc[ms][nf][3] + bv1[nf];
                        *(float2*)(out + (size_t)e1 * 64 + col) = o;
                    }
                }
            }
        }
    } else {
        // ================= PRODUCERS: 8 warps, half-row per thread ============
        const int pt = tid - 256;
        const int r = pt >> 1;       // row 0..127
        const int h = pt & 1;        // column half (0: cols 0-31, 1: cols 32-63)

        int slot = 0, phase = 1;     // phase=1: first 4 empty-waits pass immediately
        for (int tile = blockIdx.x; tile < NTILES; tile += gridDim.x) {
            int e = tile * TILE_M + r;
            if (e >= E_TOTAL) e = E_TOTAL - 1;   // clamp; stores guarded in epilogue

            // ---- chunk 0: x ----
            MBARRIER_WAIT_PARITY(EMPTY_BAR(sb, slot), phase);
            {
                const float4* xr = (const float4*)x + (size_t)e * 16 + h * 8;
                float4 v[8];
#pragma unroll
                for (int i = 0; i < 8; i++) v[i] = xr[i];
                const uint32_t base = sb + SM_A + (uint32_t)slot * 32768u;
                sts_group(base, r, 2 * h + 0, v);
                sts_group(base, r, 2 * h + 1, v + 4);
            }
            MBARRIER_ARRIVE(FULL_BAR(sb, slot));
            if (++slot == 4) { slot = 0; phase ^= 1; }

            // ---- pairs: chunks (1,2) and (3,4) ----
#pragma unroll
            for (int p = 0; p < 2; p++) {
                const int sMin = slot, phMin = phase;
                if (++slot == 4) { slot = 0; phase ^= 1; }
                const int sMax = slot, phMax = phase;
                if (++slot == 4) { slot = 0; phase ^= 1; }

                MBARRIER_WAIT_PARITY(EMPTY_BAR(sb, sMin), phMin);
                MBARRIER_WAIT_PARITY(EMPTY_BAR(sb, sMax), phMax);

                int2 nn = *(const int2*)(nbr + (size_t)e * 4 + p * 2);
                const bool aok = nn.x >= 0;
                const bool bok = nn.y >= 0;
                const float4* xa =
                    (const float4*)x + (size_t)(aok ? nn.x : 0) * 16 + h * 8;
                const float4* xb =
                    (const float4*)x + (size_t)(bok ? nn.y : 0) * 16 + h * 8;
                float4 A[8], B[8];
#pragma unroll
                for (int i = 0; i < 8; i++)
                    A[i] = aok ? xa[i] : make_float4(0.f, 0.f, 0.f, 0.f);
#pragma unroll
                for (int i = 0; i < 8; i++)
                    B[i] = bok ? xb[i] : make_float4(0.f, 0.f, 0.f, 0.f);
#pragma unroll
                for (int i = 0; i < 8; i++) {   // A <- min, B <- max (in place)
                    float4 a = A[i], b = B[i];
                    A[i] = make_float4(fminf(a.x, b.x), fminf(a.y, b.y),
                                       fminf(a.z, b.z), fminf(a.w, b.w));
                    B[i] = make_float4(fmaxf(a.x, b.x), fmaxf(a.y, b.y),
                                       fmaxf(a.z, b.z), fmaxf(a.w, b.w));
                }
                const uint32_t bMin = sb + SM_A + (uint32_t)sMin * 32768u;
                const uint32_t bMax = sb + SM_A + (uint32_t)sMax * 32768u;
                sts_group(bMin, r, 2 * h + 0, A);
                sts_group(bMin, r, 2 * h + 1, A + 4);
                sts_group(bMax, r, 2 * h + 0, B);
                sts_group(bMax, r, 2 * h + 1, B + 4);

                MBARRIER_ARRIVE(FULL_BAR(sb, sMin));
                MBARRIER_ARRIVE(FULL_BAR(sb, sMax));
            }
        }
    }
}

// ---------------- launch ----------------
extern "C" void kernel_launch(void* const* d_in, const int* in_sizes, int n_in,
                              void* d_out, int out_size) {
    const float* x   = (const float*)d_in[0];
    const int*   nbr = (const int*)d_in[1];
    const float* W   = (const float*)d_in[2];
    const float* b   = (const float*)d_in[3];
    float* out = (float*)d_out;

    int nsm = 0;
    cudaDeviceGetAttribute(&nsm, cudaDevAttrMultiProcessorCount, 0);
    if (nsm <= 0) nsm = 148;

    cudaFuncSetAttribute(meshconv_kernel,
                         cudaFuncAttributeMaxDynamicSharedMemorySize, SMEM_TOTAL);
    meshconv_kernel<<<nsm, NTHREADS, SMEM_TOTAL>>>(x, nbr, W, b, out);
}

// round 7
// speedup vs baseline: 1.5592x; 1.2500x over previous
#include <cuda_runtime.h>
#include <cstdint>

// ---------------- Problem constants ----------------
#define E_TOTAL   500000
#define TILE_M    128
#define NTILES    ((E_TOTAL + TILE_M - 1) / TILE_M)   // 3907
#define NTHREADS  512

// ---------------- SMEM layout (bytes) ----------------
// W: 5 chunks, each [64 n-rows x 64 k-cols] tf32 = 16KB -> 80KB (loaded once)
// A: 2 chunk buffers, each [128 rows x 64 k-cols] tf32 = 32KB -> 64KB
#define SM_W       0
#define SM_B0      (5 * 16384)             // 81920
#define SM_B1      (SM_B0 + 32768)         // 114688
#define SMEM_TOTAL (SM_B1 + 32768)         // 147456

// ---------------- helpers ----------------
__device__ __forceinline__ uint32_t smem_u32(const void* p) {
    uint32_t a;
    asm("{ .reg .u64 t; cvta.to.shared.u64 t, %1; cvt.u32.u64 %0, t; }"
        : "=r"(a) : "l"(p));
    return a;
}

__device__ __forceinline__ uint32_t f2tf32(float f) {
    uint32_t r;
    asm("cvt.rna.tf32.f32 %0, %1;" : "=r"(r) : "f"(f));
    return r;
}

// Tile layout: [rows x 64 cols] tf32, 256B/row. Cols k-permuted per 16-col
// group: quad (grp,tig) holds cols {16*grp+tig, +4, +8, +12} -> one LDS.128
// feeds two mma k-steps.
// Swizzle: XOR byte-offset bits[6:4] with sw(row)=((row&1)<<2)|(row&2)|((row>>2)&1).
//  - producer STS (8 consecutive rows, grp/tig fixed): sw bijective on rows 0..7 -> CF
//  - consumer LDS (rows {g,g+1} x tig 0..3, grp fixed): row parity flips bit2,
//    tig covers low half -> 8 distinct -> CF
__device__ __forceinline__ uint32_t tileoff(int row, int grp, int tig) {
    uint32_t o  = (uint32_t)(row * 256 + grp * 64 + tig * 16);
    uint32_t sw = (((uint32_t)row & 1u) << 2) | ((uint32_t)row & 2u) |
                  (((uint32_t)row >> 2) & 1u);
    return o ^ (sw << 4);
}

__device__ __forceinline__ void sts128(uint32_t addr, uint32_t a, uint32_t b,
                                       uint32_t c, uint32_t d) {
    asm volatile("st.shared.v4.b32 [%0], {%1,%2,%3,%4};"
                 :: "r"(addr), "r"(a), "r"(b), "r"(c), "r"(d) : "memory");
}

__device__ __forceinline__ void lds128(uint32_t addr, uint32_t* r) {
    asm volatile("ld.shared.v4.b32 {%0,%1,%2,%3}, [%4];"
                 : "=r"(r[0]), "=r"(r[1]), "=r"(r[2]), "=r"(r[3])
                 : "r"(addr));
}

// m16n8k8 TF32 mma (row.col): D = A*B + D
__device__ __forceinline__ void mma_tf32(float* c, uint32_t a0, uint32_t a1,
                                         uint32_t a2, uint32_t a3,
                                         uint32_t b0, uint32_t b1) {
    asm volatile(
        "mma.sync.aligned.m16n8k8.row.col.f32.tf32.tf32.f32 "
        "{%0,%1,%2,%3},{%4,%5,%6,%7},{%8,%9},{%0,%1,%2,%3};"
        : "+f"(c[0]), "+f"(c[1]), "+f"(c[2]), "+f"(c[3])
        : "r"(a0), "r"(a1), "r"(a2), "r"(a3), "r"(b0), "r"(b1));
}

// Store one 16-col group of one row (4 float4s = cols 16*grp..+15) with
// tf32 convert + k-perm repack: quad tig holds f[i*4+tig], i=0..3.
__device__ __forceinline__ void sts_chunk(uint32_t base, int row, int grp,
                                          const float4* v) {
    const float* f = (const float*)v;
#pragma unroll
    for (int t = 0; t < 4; t++) {
        sts128(base + tileoff(row, grp, t),
               f2tf32(f[0 * 4 + t]), f2tf32(f[1 * 4 + t]),
               f2tf32(f[2 * 4 + t]), f2tf32(f[3 * 4 + t]));
    }
}

// One K=64 chunk of MMA for this warp's m32 x n16 block.
__device__ __forceinline__ void mma_chunk(uint32_t aB, uint32_t wB, int wm,
                                          int wn, int g, int tig,
                                          float acc[2][2][4]) {
#pragma unroll
    for (int t = 0; t < 4; t++) {
        uint32_t Bf[2][4];
#pragma unroll
        for (int nf = 0; nf < 2; nf++)
            lds128(wB + tileoff(wn * 16 + nf * 8 + g, t, tig), Bf[nf]);
        uint32_t Af[2][2][4];
#pragma unroll
        for (int ms = 0; ms < 2; ms++)
#pragma unroll
            for (int rh = 0; rh < 2; rh++)
                lds128(aB + tileoff(wm * 32 + ms * 16 + rh * 8 + g, t, tig),
                       Af[ms][rh]);
#pragma unroll
        for (int ms = 0; ms < 2; ms++)
#pragma unroll
            for (int nf = 0; nf < 2; nf++)
#pragma unroll
                for (int s = 0; s < 2; s++)
                    mma_tf32(acc[ms][nf],
                             Af[ms][0][2 * s], Af[ms][1][2 * s],
                             Af[ms][0][2 * s + 1], Af[ms][1][2 * s + 1],
                             Bf[nf][2 * s], Bf[nf][2 * s + 1]);
    }
}

// Gather one neighbor-pair's 16-col window for row e into va/vb (0-filled if missing).
__device__ __forceinline__ void gather_pair(const float* __restrict__ x, int n0,
                                            int n1, int grp, float4* va,
                                            float4* vb) {
    const bool aok = n0 >= 0;
    const bool bok = n1 >= 0;
    const float4* pa = (const float4*)x + (size_t)(aok ? n0 : 0) * 16 + grp * 4;
    const float4* pb = (const float4*)x + (size_t)(bok ? n1 : 0) * 16 + grp * 4;
#pragma unroll
    for (int i = 0; i < 4; i++)
        va[i] = aok ? pa[i] : make_float4(0.f, 0.f, 0.f, 0.f);
#pragma unroll
    for (int i = 0; i < 4; i++)
        vb[i] = bok ? pb[i] : make_float4(0.f, 0.f, 0.f, 0.f);
}

__device__ __forceinline__ void minmax4(float4* a, float4* b) {
#pragma unroll
    for (int i = 0; i < 4; i++) {
        float4 u = a[i], v = b[i];
        a[i] = make_float4(fminf(u.x, v.x), fminf(u.y, v.y),
                           fminf(u.z, v.z), fminf(u.w, v.w));
        b[i] = make_float4(fmaxf(u.x, v.x), fmaxf(u.y, v.y),
                           fmaxf(u.z, v.z), fmaxf(u.w, v.w));
    }
}

// ---------------- kernel ----------------
// Combined layout (K=320, chunks of 64): c0:x c1:min01 c2:max01 c3:min23 c4:max23
// Uniform warps: every thread builds 1/512 of each A-chunk (row=tid&127,
// grp=tid>>7) AND participates in MMA (warp-level m32 x n16). Chunk-level
// double buffer (b0/b1) with __syncthreads(); LDGs prefetched 1+ segment ahead.
__global__ void __launch_bounds__(NTHREADS, 1)
meshconv_kernel(const float* __restrict__ x, const int* __restrict__ nbr,
                const float* __restrict__ W, const float* __restrict__ bias,
                float* __restrict__ out) {
    extern __shared__ char smem[];
    const uint32_t sb = smem_u32(smem);
    const int tid = threadIdx.x;

    // Producer identity
    const int r   = tid & 127;
    const int grp = tid >> 7;
    // Consumer identity
    const int wid = tid >> 5, lid = tid & 31;
    const int wm = wid & 3, wn = wid >> 2;
    const int g = lid >> 2, tig = lid & 3;

    const uint32_t b0 = sb + SM_B0;
    const uint32_t b1 = sb + SM_B1;

    // ---- prologue LDGs for first tile (issue before W staging to overlap) ----
    int tile = blockIdx.x;
    int e = tile * TILE_M + r;
    if (e >= E_TOTAL) e = E_TOTAL - 1;
    int4 nb4 = __ldg((const int4*)(nbr + (size_t)e * 4));
    float4 xq[4];
    {
        const float4* px = (const float4*)x + (size_t)e * 16 + grp * 4;
#pragma unroll
        for (int i = 0; i < 4; i++) xq[i] = px[i];
    }
    float4 P0a[4], P0b[4];
    gather_pair(x, nb4.x, nb4.y, grp, P0a, P0b);

    // ---- stage W once: 1280 group-tasks (n-row major => CF stores) ----
#pragma unroll
    for (int it = 0; it < 3; it++) {
        int t = tid + it * NTHREADS;
        if (t < 1280) {
            int c = t / 256;            // chunk 0..4
            int rem = t & 255;
            int n = rem & 63;           // n-row (row-major within warp => CF)
            int gw = rem >> 6;          // group 0..3
            float4 v[4];
#pragma unroll
            for (int i = 0; i < 4; i++)
                v[i] = ((const float4*)W)[(size_t)n * 80 + c * 16 + gw * 4 + i];
            sts_chunk(sb + SM_W + (uint32_t)c * 16384u, n, gw, v);
        }
    }

    // bias fragment
    float bv[2][2];
#pragma unroll
    for (int nf = 0; nf < 2; nf++) {
        int bc = wn * 16 + nf * 8 + tig * 2;
        bv[nf][0] = __ldg(bias + bc);
        bv[nf][1] = __ldg(bias + bc + 1);
    }
    __syncthreads();

    for (; tile < NTILES; tile += gridDim.x) {
        float acc[2][2][4];
#pragma unroll
        for (int a = 0; a < 2; a++)
#pragma unroll
            for (int b = 0; b < 2; b++)
#pragma unroll
                for (int k = 0; k < 4; k++) acc[a][b][k] = 0.f;

        // seg -1: stage c0 (x)
        sts_chunk(b0, r, grp, xq);
        __syncthreads();

        // seg 0: minmax p0; STS c1(min01)->b1; prefetch pair1; mma c0(b0)
        minmax4(P0a, P0b);
        sts_chunk(b1, r, grp, P0a);
        float4 P1a[4], P1b[4];
        gather_pair(x, nb4.z, nb4.w, grp, P1a, P1b);
        mma_chunk(b0, sb + SM_W + 0 * 16384u, wm, wn, g, tig, acc);
        __syncthreads();

        // seg 1: STS c2(max01)->b0; mma c1(b1)
        sts_chunk(b0, r, grp, P0b);
        mma_chunk(b1, sb + SM_W + 1 * 16384u, wm, wn, g, tig, acc);
        __syncthreads();

        // seg 2: minmax p1; STS c3(min23)->b1; prefetch next nbr; mma c2(b0)
        minmax4(P1a, P1b);
        sts_chunk(b1, r, grp, P1a);
        int tn = tile + gridDim.x;
        if (tn >= NTILES) tn = tile;
        int en = tn * TILE_M + r;
        if (en >= E_TOTAL) en = E_TOTAL - 1;
        int4 nb4n = __ldg((const int4*)(nbr + (size_t)en * 4));
        mma_chunk(b0, sb + SM_W + 2 * 16384u, wm, wn, g, tig, acc);
        __syncthreads();

        // seg 3: STS c4(max23)->b0; prefetch next x row; mma c3(b1)
        sts_chunk(b0, r, grp, P1b);
        {
            const float4* px = (const float4*)x + (size_t)en * 16 + grp * 4;
#pragma unroll
            for (int i = 0; i < 4; i++) xq[i] = px[i];
        }
        mma_chunk(b1, sb + SM_W + 3 * 16384u, wm, wn, g, tig, acc);
        __syncthreads();

        // seg 4: mma c4(b0); prefetch next pair0; epilogue
        mma_chunk(b0, sb + SM_W + 4 * 16384u, wm, wn, g, tig, acc);
        nb4 = nb4n;
        gather_pair(x, nb4.x, nb4.y, grp, P0a, P0b);

#pragma unroll
        for (int ms = 0; ms < 2; ms++) {
#pragma unroll
            for (int nf = 0; nf < 2; nf++) {
                const int e0  = tile * TILE_M + wm * 32 + ms * 16 + g;
                const int e1  = e0 + 8;
                const int col = wn * 16 + nf * 8 + tig * 2;
                if (e0 < E_TOTAL) {
                    float2 o;
                    o.x = acc[ms][nf][0] + bv[nf][0];
                    o.y = acc[ms][nf][1] + bv[nf][1];
                    *(float2*)(out + (size_t)e0 * 64 + col) = o;
                }
                if (e1 < E_TOTAL) {
                    float2 o;
                    o.x = acc[ms][nf][2] + bv[nf][0];
                    o.y = acc[ms][nf][3] + bv[nf][1];
                    *(float2*)(out + (size_t)e1 * 64 + col) = o;
                }
            }
        }
        __syncthreads();   // protect b0 against next tile's STS c0
    }
}

// ---------------- launch ----------------
extern "C" void kernel_launch(void* const* d_in, const int* in_sizes, int n_in,
                              void* d_out, int out_size) {
    const float* x   = (const float*)d_in[0];
    const int*   nbr = (const int*)d_in[1];
    const float* W   = (const float*)d_in[2];
    const float* b   = (const float*)d_in[3];
    float* out = (float*)d_out;

    int nsm = 0;
    cudaDeviceGetAttribute(&nsm, cudaDevAttrMultiProcessorCount, 0);
    if (nsm <= 0) nsm = 148;

    cudaFuncSetAttribute(meshconv_kernel,
                         cudaFuncAttributeMaxDynamicSharedMemorySize, SMEM_TOTAL);
    meshconv_kernel<<<nsm, NTHREADS, SMEM_TOTAL>>>(x, nbr, W, b, out);
}

// round 8
// speedup vs baseline: 2.2044x; 1.4138x over previous
#include <cuda_runtime.h>
#include <cstdint>

// ---------------- Problem constants ----------------
#define E_TOTAL   500000
#define TILE_M    128
#define NTILES    ((E_TOTAL + TILE_M - 1) / TILE_M)   // 3907
#define NTHREADS  256

// ---------------- SMEM layout (bytes) ----------------
// W: 5 chunks, each [64 n x 64 k] tf32 = 16KB -> 80KB (loaded once)
// A: 2 chunk buffers [128 rows x 64 k] tf32 = 32KB each
#define SM_W       0
#define SM_B0      (5 * 16384)             // 81920
#define SM_B1      (SM_B0 + 32768)         // 114688
#define SMEM_TOTAL (SM_B1 + 32768)         // 147456

// ---------------- helpers ----------------
__device__ __forceinline__ uint32_t smem_u32(const void* p) {
    uint32_t a;
    asm("{ .reg .u64 t; cvta.to.shared.u64 t, %1; cvt.u32.u64 %0, t; }"
        : "=r"(a) : "l"(p));
    return a;
}

__device__ __forceinline__ uint32_t f2tf32(float f) {
    uint32_t r;
    asm("cvt.rna.tf32.f32 %0, %1;" : "=r"(r) : "f"(f));
    return r;
}

// Tile layout: [rows x 64 cols] tf32, 256B/row, cols k-permuted per 16-col
// group: quad (grp,t) holds cols {16grp+t, +4, +8, +12}.
// Swizzle: XOR byte bits[6:4] with sw(row)=((row&1)<<2)|(row&2)|((row>>2)&1).
__device__ __forceinline__ uint32_t tileoff(int row, int grp, int t) {
    uint32_t o  = (uint32_t)(row * 256 + grp * 64 + t * 16);
    uint32_t sw = (((uint32_t)row & 1u) << 2) | ((uint32_t)row & 2u) |
                  (((uint32_t)row >> 2) & 1u);
    return o ^ (sw << 4);
}

__device__ __forceinline__ void sts128(uint32_t addr, uint32_t a, uint32_t b,
                                       uint32_t c, uint32_t d) {
    asm volatile("st.shared.v4.b32 [%0], {%1,%2,%3,%4};"
                 :: "r"(addr), "r"(a), "r"(b), "r"(c), "r"(d) : "memory");
}

__device__ __forceinline__ void lds128(uint32_t addr, uint32_t* r) {
    asm volatile("ld.shared.v4.b32 {%0,%1,%2,%3}, [%4];"
                 : "=r"(r[0]), "=r"(r[1]), "=r"(r[2]), "=r"(r[3])
                 : "r"(addr));
}

__device__ __forceinline__ void mma_tf32(float* c, uint32_t a0, uint32_t a1,
                                         uint32_t a2, uint32_t a3,
                                         uint32_t b0, uint32_t b1) {
    asm volatile(
        "mma.sync.aligned.m16n8k8.row.col.f32.tf32.tf32.f32 "
        "{%0,%1,%2,%3},{%4,%5,%6,%7},{%8,%9},{%0,%1,%2,%3};"
        : "+f"(c[0]), "+f"(c[1]), "+f"(c[2]), "+f"(c[3])
        : "r"(a0), "r"(a1), "r"(a2), "r"(a3), "r"(b0), "r"(b1));
}

// 4x4 transpose across 4 consecutive lanes (sub = lane&3), in-place on v.
// After: lane sub=t holds {M[0][t],M[1][t],M[2][t],M[3][t]} where M[i] is
// lane base+i's original float4 -> exactly the k-permuted quad.
__device__ __forceinline__ void transpose4(float4& v, int sub) {
    float t0 = (sub & 1) ? v.x : v.y;
    float t1 = (sub & 1) ? v.z : v.w;
    t0 = __shfl_xor_sync(0xffffffffu, t0, 1);
    t1 = __shfl_xor_sync(0xffffffffu, t1, 1);
    if (sub & 1) { v.x = t0; v.z = t1; } else { v.y = t0; v.w = t1; }
    float t2 = (sub & 2) ? v.x : v.z;
    float t3 = (sub & 2) ? v.y : v.w;
    t2 = __shfl_xor_sync(0xffffffffu, t2, 2);
    t3 = __shfl_xor_sync(0xffffffffu, t3, 2);
    if (sub & 2) { v.x = t2; v.y = t3; } else { v.z = t2; v.w = t3; }
}

// In-thread repack used for W staging (thread holds all 4 quads of a group).
__device__ __forceinline__ void sts_group_w(uint32_t base, int row, int grp,
                                            const float4* v) {
    const float* f = (const float*)v;
#pragma unroll
    for (int t = 0; t < 4; t++) {
        sts128(base + tileoff(row, grp, t),
               f2tf32(f[0 * 4 + t]), f2tf32(f[1 * 4 + t]),
               f2tf32(f[2 * 4 + t]), f2tf32(f[3 * 4 + t]));
    }
}

// ---- cooperative gather/store streams (warp = 16 edges, 8 passes of 2) ----
// Lane: q = lid&15 (quad within 256B row), half = lid>>4 (edge parity).
__device__ __forceinline__ void gather_x8(const float* __restrict__ x, int base,
                                          int q, int half, float4* D) {
#pragma unroll
    for (int k = 0; k < 8; k++) {
        int e = base + 2 * k + half;
        if (e > E_TOTAL - 1) e = E_TOTAL - 1;
        D[k] = __ldg((const float4*)x + (size_t)e * 16 + q);
    }
}

// comp: lanes 0..15 hold neighbor index for edge we0+lane.
__device__ __forceinline__ void gather_nbr8(const float* __restrict__ x, int comp,
                                            int q, int half, float4* D) {
#pragma unroll
    for (int k = 0; k < 8; k++) {
        int idx = __shfl_sync(0xffffffffu, comp, 2 * k + half);
        float4 v = make_float4(0.f, 0.f, 0.f, 0.f);
        if (idx >= 0) v = __ldg((const float4*)x + (size_t)idx * 16 + q);
        D[k] = v;
    }
}

__device__ __forceinline__ void minmax8(float4* a, float4* b) {
#pragma unroll
    for (int i = 0; i < 8; i++) {
        float4 u = a[i], v = b[i];
        a[i] = make_float4(fminf(u.x, v.x), fminf(u.y, v.y),
                           fminf(u.z, v.z), fminf(u.w, v.w));
        b[i] = make_float4(fmaxf(u.x, v.x), fmaxf(u.y, v.y),
                           fmaxf(u.z, v.z), fmaxf(u.w, v.w));
    }
}

// Transpose (cross-lane) + convert + STS a whole stream (consumes S's values).
__device__ __forceinline__ void xpose_sts8(uint32_t buf, int we0, int half,
                                           int grp, int sub, const float4* S) {
#pragma unroll
    for (int k = 0; k < 8; k++) {
        float4 v = S[k];
        transpose4(v, sub);
        int row = we0 + 2 * k + half;
        sts128(buf + tileoff(row, grp, sub),
               f2tf32(v.x), f2tf32(v.y), f2tf32(v.z), f2tf32(v.w));
    }
}

// One K=64 chunk of MMA for this warp's m32 x n32 block.
__device__ __forceinline__ void mma_chunk(uint32_t aB, uint32_t wB, int wm,
                                          int wn, int g, int tig,
                                          float acc[2][4][4]) {
#pragma unroll
    for (int t = 0; t < 4; t++) {
        uint32_t Bf[4][4];
#pragma unroll
        for (int nf = 0; nf < 4; nf++)
            lds128(wB + tileoff(wn * 32 + nf * 8 + g, t, tig), Bf[nf]);
        uint32_t Af[2][2][4];
#pragma unroll
        for (int ms = 0; ms < 2; ms++)
#pragma unroll
            for (int rh = 0; rh < 2; rh++)
                lds128(aB + tileoff(wm * 32 + ms * 16 + rh * 8 + g, t, tig),
                       Af[ms][rh]);
#pragma unroll
        for (int ms = 0; ms < 2; ms++)
#pragma unroll
            for (int nf = 0; nf < 4; nf++)
#pragma unroll
                for (int s = 0; s < 2; s++)
                    mma_tf32(acc[ms][nf],
                             Af[ms][0][2 * s], Af[ms][1][2 * s],
                             Af[ms][0][2 * s + 1], Af[ms][1][2 * s + 1],
                             Bf[nf][2 * s], Bf[nf][2 * s + 1]);
    }
}

// ---------------- kernel ----------------
// K=320 chunks: c0:x  c1:min01  c2:max01  c3:min23  c4:max23
// 256 threads, 8 warps: uniform roles. Gathers warp-cooperative (coalesced),
// repack via cross-lane 4x4 transpose; chunk double-buffer (b0/b1) pipeline.
__global__ void __launch_bounds__(NTHREADS, 1)
meshconv_kernel(const float* __restrict__ x, const int* __restrict__ nbr,
                const float* __restrict__ W, const float* __restrict__ bias,
                float* __restrict__ out) {
    extern __shared__ char smem[];
    const uint32_t sb = smem_u32(smem);
    const int tid = threadIdx.x;
    const int lid = tid & 31, wid = tid >> 5;
    // consumer identity (m32 x n32 per warp; 4 warps in m, 2 in n)
    const int wm = wid & 3, wn = wid >> 2;
    const int g = lid >> 2, tig = lid & 3;
    // producer identity (warp owns 16 edges)
    const int q = lid & 15, half = lid >> 4, sub = lid & 3, grp = q >> 2;
    const int we0 = wid * 16;

    const uint32_t b0 = sb + SM_B0, b1 = sb + SM_B1;

    // ---- stage W once: it == chunk, tid -> (n, group) ----
#pragma unroll
    for (int c = 0; c < 5; c++) {
        int n = tid & 63;
        int gw = tid >> 6;
        float4 v[4];
#pragma unroll
        for (int i = 0; i < 4; i++)
            v[i] = ((const float4*)W)[(size_t)n * 80 + c * 16 + gw * 4 + i];
        sts_group_w(sb + SM_W + (uint32_t)c * 16384u, n, gw, v);
    }

    // bias fragment
    float bv[4][2];
#pragma unroll
    for (int nf = 0; nf < 4; nf++) {
        int bc = wn * 32 + nf * 8 + tig * 2;
        bv[nf][0] = __ldg(bias + bc);
        bv[nf][1] = __ldg(bias + bc + 1);
    }

    // ---- prologue gathers for first tile ----
    int tile = blockIdx.x;
    int base = tile * TILE_M + we0;
    int4 NB = make_int4(-1, -1, -1, -1);
    {
        int e = base + (lid & 15);
        if (e > E_TOTAL - 1) e = E_TOTAL - 1;
        if (lid < 16) NB = __ldg((const int4*)nbr + e);
    }
    float4 XQ[8];
    gather_x8(x, base, q, half, XQ);
    float4 A0[8], B0[8];
    gather_nbr8(x, NB.x, q, half, A0);
    gather_nbr8(x, NB.y, q, half, B0);

    __syncthreads();   // W staged

    for (; tile < NTILES; tile += gridDim.x) {
        int tn = tile + gridDim.x;
        if (tn >= NTILES) tn = tile;
        const int nbase = tn * TILE_M + we0;

        float acc[2][4][4];
#pragma unroll
        for (int a = 0; a < 2; a++)
#pragma unroll
            for (int b = 0; b < 4; b++)
#pragma unroll
                for (int k = 0; k < 4; k++) acc[a][b][k] = 0.f;

        // s-1: STS c0 (x) -> b0
        xpose_sts8(b0, we0, half, grp, sub, XQ);
        __syncthreads();

        // s0: issue A1; minmax pair0; STS c1(min01)->b1; mma c0(b0)
        float4 A1[8], B1[8];
        gather_nbr8(x, NB.z, q, half, A1);
        minmax8(A0, B0);
        xpose_sts8(b1, we0, half, grp, sub, A0);
        mma_chunk(b0, sb + SM_W + 0 * 16384u, wm, wn, g, tig, acc);
        __syncthreads();

        // s1: issue B1; STS c2(max01)->b0; mma c1(b1)
        gather_nbr8(x, NB.w, q, half, B1);
        xpose_sts8(b0, we0, half, grp, sub, B0);
        mma_chunk(b1, sb + SM_W + 1 * 16384u, wm, wn, g, tig, acc);
        __syncthreads();

        // s2: minmax pair1; STS c3(min23)->b1; prefetch next x + nbr; mma c2(b0)
        minmax8(A1, B1);
        xpose_sts8(b1, we0, half, grp, sub, A1);
        gather_x8(x, nbase, q, half, XQ);
        int4 NBn = make_int4(-1, -1, -1, -1);
        {
            int e = nbase + (lid & 15);
            if (e > E_TOTAL - 1) e = E_TOTAL - 1;
            if (lid < 16) NBn = __ldg((const int4*)nbr + e);
        }
        mma_chunk(b0, sb + SM_W + 2 * 16384u, wm, wn, g, tig, acc);
        __syncthreads();

        // s3: STS c4(max23)->b0; issue next A0; mma c3(b1)
        xpose_sts8(b0, we0, half, grp, sub, B1);
        gather_nbr8(x, NBn.x, q, half, A0);
        mma_chunk(b1, sb + SM_W + 3 * 16384u, wm, wn, g, tig, acc);
        __syncthreads();

        // s4: mma c4(b0); issue next B0; epilogue
        mma_chunk(b0, sb + SM_W + 4 * 16384u, wm, wn, g, tig, acc);
        gather_nbr8(x, NBn.y, q, half, B0);
        NB = NBn;

#pragma unroll
        for (int ms = 0; ms < 2; ms++) {
#pragma unroll
            for (int nf = 0; nf < 4; nf++) {
                const int e0  = tile * TILE_M + wm * 32 + ms * 16 + g;
                const int e1  = e0 + 8;
                const int col = wn * 32 + nf * 8 + tig * 2;
                if (e0 < E_TOTAL) {
                    float2 o;
                    o.x = acc[ms][nf][0] + bv[nf][0];
                    o.y = acc[ms][nf][1] + bv[nf][1];
                    *(float2*)(out + (size_t)e0 * 64 + col) = o;
                }
                if (e1 < E_TOTAL) {
                    float2 o;
                    o.x = acc[ms][nf][2] + bv[nf][0];
                    o.y = acc[ms][nf][3] + bv[nf][1];
                    *(float2*)(out + (size_t)e1 * 64 + col) = o;
                }
            }
        }
        __syncthreads();   // protect b0 before next tile's STS c0
    }
}

// ---------------- launch ----------------
extern "C" void kernel_launch(void* const* d_in, const int* in_sizes, int n_in,
                              void* d_out, int out_size) {
    const float* x   = (const float*)d_in[0];
    const int*   nbr = (const int*)d_in[1];
    const float* W   = (const float*)d_in[2];
    const float* b   = (const float*)d_in[3];
    float* out = (float*)d_out;

    int nsm = 0;
    cudaDeviceGetAttribute(&nsm, cudaDevAttrMultiProcessorCount, 0);
    if (nsm <= 0) nsm = 148;

    cudaFuncSetAttribute(meshconv_kernel,
                         cudaFuncAttributeMaxDynamicSharedMemorySize, SMEM_TOTAL);
    meshconv_kernel<<<nsm, NTHREADS, SMEM_TOTAL>>>(x, nbr, W, b, out);
}